// round 5
// baseline (speedup 1.0000x reference)
#include <cuda_runtime.h>
#include <cuda_bf16.h>

#define NUM_P 41          // pred labels 0..40
#define NUM_C 26          // gt labels 0..25
#define HIST_BLOCKS 888   // 148 SMs * 6
#define HIST_THREADS 128  // 4 warps
#define NWARP 4

// Global scratch
__device__ unsigned int g_pred_counts[NUM_P];
__device__ unsigned int g_gt_counts[NUM_C];
__device__ unsigned int g_omask[NUM_P];   // bit c set <=> some voxel has pred==p, gt==c

__global__ void zero_counts_kernel() {
    int t = threadIdx.x;
    if (t < NUM_P) g_pred_counts[t] = 0u;
    if (t < NUM_C) g_gt_counts[t] = 0u;
    if (t < NUM_P) g_omask[t] = 0u;
}

__device__ __forceinline__ float warp_sum_u32(unsigned int v) {
    float f = (float)v;  // counts small; stay in u32 actually
    return f;
}

__global__ void __launch_bounds__(HIST_THREADS)
hist_kernel(const float4* __restrict__ pred4, const int4* __restrict__ gt4,
            const float* __restrict__ pred, const int* __restrict__ gt,
            int n4, int n) {
    // Per-warp, per-lane exclusive histogram columns: h[warp][bin][lane]
    __shared__ unsigned int s_pred[NWARP][NUM_P * 32];
    __shared__ unsigned int s_gt[NWARP][NUM_C * 32];
    __shared__ unsigned int s_om[NUM_P];

    const int t = threadIdx.x;
    const int lane = t & 31;
    const int w = t >> 5;

    // zero smem
    {
        unsigned int* sp = &s_pred[0][0];
        for (int i = t; i < NWARP * NUM_P * 32; i += HIST_THREADS) sp[i] = 0u;
        unsigned int* sg = &s_gt[0][0];
        for (int i = t; i < NWARP * NUM_C * 32; i += HIST_THREADS) sg[i] = 0u;
        if (t < NUM_P) s_om[t] = 0u;
    }
    __syncthreads();

    unsigned int* mp = &s_pred[w][lane];  // index by p*32
    unsigned int* mg = &s_gt[w][lane];    // index by g*32

    const int stride = gridDim.x * HIST_THREADS;
    int i = blockIdx.x * HIST_THREADS + t;

    for (; i + stride < n4; i += 2 * stride) {
        float4 p0 = pred4[i];
        int4   g0 = gt4[i];
        float4 p1 = pred4[i + stride];
        int4   g1 = gt4[i + stride];

        int pa = __float2int_rn(p0.x), pb = __float2int_rn(p0.y);
        int pc = __float2int_rn(p0.z), pd = __float2int_rn(p0.w);
        int pe = __float2int_rn(p1.x), pf = __float2int_rn(p1.y);
        int pg = __float2int_rn(p1.z), ph = __float2int_rn(p1.w);

        mg[g0.x * 32] += 1u;  mp[pa * 32] += 1u;
        mg[g0.y * 32] += 1u;  mp[pb * 32] += 1u;
        mg[g0.z * 32] += 1u;  mp[pc * 32] += 1u;
        mg[g0.w * 32] += 1u;  mp[pd * 32] += 1u;
        mg[g1.x * 32] += 1u;  mp[pe * 32] += 1u;
        mg[g1.y * 32] += 1u;  mp[pf * 32] += 1u;
        mg[g1.z * 32] += 1u;  mp[pg * 32] += 1u;
        mg[g1.w * 32] += 1u;  mp[ph * 32] += 1u;

        // overlap bits: check-then-set (atomic is rare after warm-up)
        if (!((s_om[pa] >> g0.x) & 1u)) atomicOr(&s_om[pa], 1u << g0.x);
        if (!((s_om[pb] >> g0.y) & 1u)) atomicOr(&s_om[pb], 1u << g0.y);
        if (!((s_om[pc] >> g0.z) & 1u)) atomicOr(&s_om[pc], 1u << g0.z);
        if (!((s_om[pd] >> g0.w) & 1u)) atomicOr(&s_om[pd], 1u << g0.w);
        if (!((s_om[pe] >> g1.x) & 1u)) atomicOr(&s_om[pe], 1u << g1.x);
        if (!((s_om[pf] >> g1.y) & 1u)) atomicOr(&s_om[pf], 1u << g1.y);
        if (!((s_om[pg] >> g1.z) & 1u)) atomicOr(&s_om[pg], 1u << g1.z);
        if (!((s_om[ph] >> g1.w) & 1u)) atomicOr(&s_om[ph], 1u << g1.w);
    }
    for (; i < n4; i += stride) {
        float4 p = pred4[i];
        int4   g = gt4[i];
        int pa = __float2int_rn(p.x), pb = __float2int_rn(p.y);
        int pc = __float2int_rn(p.z), pd = __float2int_rn(p.w);
        mg[g.x * 32] += 1u;  mp[pa * 32] += 1u;
        mg[g.y * 32] += 1u;  mp[pb * 32] += 1u;
        mg[g.z * 32] += 1u;  mp[pc * 32] += 1u;
        mg[g.w * 32] += 1u;  mp[pd * 32] += 1u;
        if (!((s_om[pa] >> g.x) & 1u)) atomicOr(&s_om[pa], 1u << g.x);
        if (!((s_om[pb] >> g.y) & 1u)) atomicOr(&s_om[pb], 1u << g.y);
        if (!((s_om[pc] >> g.z) & 1u)) atomicOr(&s_om[pc], 1u << g.z);
        if (!((s_om[pd] >> g.w) & 1u)) atomicOr(&s_om[pd], 1u << g.w);
    }
    // scalar tail
    int tail_start = n4 * 4;
    for (int j = tail_start + blockIdx.x * HIST_THREADS + t; j < n; j += stride) {
        int p = __float2int_rn(pred[j]);
        int g = gt[j];
        mg[g * 32] += 1u;
        mp[p * 32] += 1u;
        if (!((s_om[p] >> g) & 1u)) atomicOr(&s_om[p], 1u << g);
    }

    __syncthreads();

    // Flush: each warp reduces its own copies (conflict-free LDS + shfl)
    for (int b = 0; b < NUM_P; b++) {
        unsigned int v = s_pred[w][b * 32 + lane];
        #pragma unroll
        for (int o = 16; o > 0; o >>= 1) v += __shfl_down_sync(0xFFFFFFFFu, v, o);
        if (lane == 0 && v) atomicAdd(&g_pred_counts[b], v);
    }
    for (int b = 0; b < NUM_C; b++) {
        unsigned int v = s_gt[w][b * 32 + lane];
        #pragma unroll
        for (int o = 16; o > 0; o >>= 1) v += __shfl_down_sync(0xFFFFFFFFu, v, o);
        if (lane == 0 && v) atomicAdd(&g_gt_counts[b], v);
    }
    if (t < NUM_P && s_om[t]) atomicOr(&g_omask[t], s_om[t]);
}

// Single block, 64 threads: the 41x26 reduction to the scalar loss.
__global__ void __launch_bounds__(64)
finalize_kernel(float* __restrict__ out) {
    __shared__ float        s_pred_sizes[NUM_P];
    __shared__ unsigned int s_omask[NUM_P];
    __shared__ float        s_gt_sizes[NUM_C];
    __shared__ unsigned int s_present;
    __shared__ float        s_dice[64];
    __shared__ float        s_fp[64];

    const int t = threadIdx.x;

    if (t < NUM_P) {
        s_pred_sizes[t] = (float)g_pred_counts[t];
        s_omask[t] = g_omask[t];   // bit 0 (gt==0) present but masked out below
    }
    if (t < NUM_C) s_gt_sizes[t] = (float)g_gt_counts[t];
    __syncthreads();

    if (t == 0) {
        unsigned int pm = 0u;
        for (int c = 1; c < NUM_C; c++)
            if (s_gt_sizes[c] > 0.0f) pm |= (1u << c);
        s_present = pm;
    }
    __syncthreads();
    const unsigned int pm = s_present;

    float contrib = 0.0f;
    if (t >= 1 && t < NUM_C && ((pm >> t) & 1u)) {
        float us = 0.0f;
        #pragma unroll
        for (int p = 0; p < NUM_P; p++)
            if ((s_omask[p] >> t) & 1u) us += s_pred_sizes[p];
        contrib = 2.0f * s_gt_sizes[t] / (us + s_gt_sizes[t] + 1.0f);
    }
    float fpc = 0.0f;
    if (t < NUM_P && s_pred_sizes[t] > 0.0f && (s_omask[t] & pm) == 0u)
        fpc = 1.0f;

    s_dice[t] = contrib;
    s_fp[t]   = fpc;
    __syncthreads();

    if (t == 0) {
        float lesion_dice = 0.0f, fp = 0.0f;
        for (int i = 0; i < 64; i++) { lesion_dice += s_dice[i]; fp += s_fp[i]; }
        float num_gt = (float)__popc(pm);
        out[0] = lesion_dice / (num_gt + fp);
    }
}

extern "C" void kernel_launch(void* const* d_in, const int* in_sizes, int n_in,
                              void* d_out, int out_size) {
    const float* pred = (const float*)d_in[0];
    const int*   gt   = (const int*)d_in[1];
    float* out = (float*)d_out;
    const int n  = in_sizes[0];
    const int n4 = n >> 2;

    zero_counts_kernel<<<1, 64>>>();
    hist_kernel<<<HIST_BLOCKS, HIST_THREADS>>>(
        (const float4*)pred, (const int4*)gt, pred, gt, n4, n);
    finalize_kernel<<<1, 64>>>(out);
}

// round 6
// speedup vs baseline: 4.0923x; 4.0923x over previous
#include <cuda_runtime.h>
#include <cuda_bf16.h>

#define NUM_P 41          // pred labels 0..40
#define NUM_C 26          // gt labels 0..25
#define BINS  (NUM_P * NUM_C)   // 1066
#define HIST_BLOCKS 1184        // 148 SMs * 8
#define HIST_THREADS 256

// Global scratch (zero at module load; reset by the last block each run)
__device__ unsigned int g_counts[BINS];
__device__ unsigned int g_ticket;

__global__ void __launch_bounds__(HIST_THREADS)
fused_kernel(const float4* __restrict__ pred4, const int4* __restrict__ gt4,
             const float* __restrict__ pred, const int* __restrict__ gt,
             int n4, int n, float* __restrict__ out) {
    __shared__ unsigned int h[BINS];
    for (int i = threadIdx.x; i < BINS; i += HIST_THREADS) h[i] = 0u;
    __syncthreads();

    const int stride = gridDim.x * HIST_THREADS;
    int i = blockIdx.x * HIST_THREADS + threadIdx.x;

    // Main loop: 2 float4 + 2 int4 loads in flight per iteration (MLP ~4),
    // one joint-bin smem atomic per voxel (at the spread-ATOMS LSU floor).
    for (; i + stride < n4; i += 2 * stride) {
        float4 p0 = pred4[i];
        int4   g0 = gt4[i];
        float4 p1 = pred4[i + stride];
        int4   g1 = gt4[i + stride];
        atomicAdd(&h[__float2int_rn(p0.x) * NUM_C + g0.x], 1u);
        atomicAdd(&h[__float2int_rn(p0.y) * NUM_C + g0.y], 1u);
        atomicAdd(&h[__float2int_rn(p0.z) * NUM_C + g0.z], 1u);
        atomicAdd(&h[__float2int_rn(p0.w) * NUM_C + g0.w], 1u);
        atomicAdd(&h[__float2int_rn(p1.x) * NUM_C + g1.x], 1u);
        atomicAdd(&h[__float2int_rn(p1.y) * NUM_C + g1.y], 1u);
        atomicAdd(&h[__float2int_rn(p1.z) * NUM_C + g1.z], 1u);
        atomicAdd(&h[__float2int_rn(p1.w) * NUM_C + g1.w], 1u);
    }
    for (; i < n4; i += stride) {
        float4 p = pred4[i];
        int4   g = gt4[i];
        atomicAdd(&h[__float2int_rn(p.x) * NUM_C + g.x], 1u);
        atomicAdd(&h[__float2int_rn(p.y) * NUM_C + g.y], 1u);
        atomicAdd(&h[__float2int_rn(p.z) * NUM_C + g.z], 1u);
        atomicAdd(&h[__float2int_rn(p.w) * NUM_C + g.w], 1u);
    }
    int tail_start = n4 * 4;
    for (int j = tail_start + blockIdx.x * HIST_THREADS + threadIdx.x; j < n;
         j += stride) {
        atomicAdd(&h[__float2int_rn(pred[j]) * NUM_C + gt[j]], 1u);
    }

    __syncthreads();
    // Flush block-private histogram to global
    for (int k = threadIdx.x; k < BINS; k += HIST_THREADS) {
        unsigned int v = h[k];
        if (v) atomicAdd(&g_counts[k], v);
    }
    __threadfence();

    // Last-block-done election
    __shared__ unsigned int s_last;
    if (threadIdx.x == 0)
        s_last = (atomicAdd(&g_ticket, 1u) == (unsigned)gridDim.x - 1u) ? 1u : 0u;
    __syncthreads();
    if (!s_last) return;
    __threadfence();  // acquire: all blocks' flushes visible

    // ---- Inline finalize (the 41x26 reduction), 256 threads available ----
    __shared__ float        s_pred_sizes[NUM_P];
    __shared__ unsigned int s_omask[NUM_P];
    __shared__ float        s_gt_sizes[NUM_C];
    __shared__ unsigned int s_present;
    __shared__ float        s_dice[64];
    __shared__ float        s_fp[64];

    const int t = threadIdx.x;

    if (t < NUM_P) {
        float ps = 0.0f;
        unsigned int m = 0u;
        #pragma unroll
        for (int c = 0; c < NUM_C; c++) {
            unsigned int v = g_counts[t * NUM_C + c];
            ps += (float)v;
            if (c >= 1 && v) m |= (1u << c);
        }
        s_pred_sizes[t] = ps;
        s_omask[t] = m;
    }
    if (t < NUM_C) {
        float gs = 0.0f;
        #pragma unroll
        for (int p = 0; p < NUM_P; p++)
            gs += (float)g_counts[p * NUM_C + t];
        s_gt_sizes[t] = gs;
    }
    __syncthreads();

    if (t == 0) {
        unsigned int pm = 0u;
        for (int c = 1; c < NUM_C; c++)
            if (s_gt_sizes[c] > 0.0f) pm |= (1u << c);
        s_present = pm;
    }
    __syncthreads();
    const unsigned int pm = s_present;

    if (t < 64) {
        float contrib = 0.0f;
        if (t >= 1 && t < NUM_C && ((pm >> t) & 1u)) {
            float us = 0.0f;
            #pragma unroll
            for (int p = 0; p < NUM_P; p++)
                if ((s_omask[p] >> t) & 1u) us += s_pred_sizes[p];
            contrib = 2.0f * s_gt_sizes[t] / (us + s_gt_sizes[t] + 1.0f);
        }
        float fpc = 0.0f;
        if (t < NUM_P && s_pred_sizes[t] > 0.0f && (s_omask[t] & pm) == 0u)
            fpc = 1.0f;
        s_dice[t] = contrib;
        s_fp[t]   = fpc;
    }
    __syncthreads();

    if (t == 0) {
        float lesion_dice = 0.0f, fp = 0.0f;
        for (int k = 0; k < 64; k++) { lesion_dice += s_dice[k]; fp += s_fp[k]; }
        float num_gt = (float)__popc(pm);
        out[0] = lesion_dice / (num_gt + fp);
    }
    __syncthreads();

    // Reset scratch for the next run / graph replay (deterministic)
    for (int k = t; k < BINS; k += HIST_THREADS) g_counts[k] = 0u;
    if (t == 0) g_ticket = 0u;
}

extern "C" void kernel_launch(void* const* d_in, const int* in_sizes, int n_in,
                              void* d_out, int out_size) {
    const float* pred = (const float*)d_in[0];
    const int*   gt   = (const int*)d_in[1];
    float* out = (float*)d_out;
    const int n  = in_sizes[0];
    const int n4 = n >> 2;

    fused_kernel<<<HIST_BLOCKS, HIST_THREADS>>>(
        (const float4*)pred, (const int4*)gt, pred, gt, n4, n, out);
}